// round 4
// baseline (speedup 1.0000x reference)
#include <cuda_runtime.h>

#define BB 128
#define NN 100
#define EE 3200
#define NT 512

struct Args {
    const float* nodes;
    const int*   ei;
    const float* ea;
    const int*   agent;
    const float* emb;
    const float *W1,*b1,*W2,*b2,*W3,*b3,*lng,*lnb;
    const float *g1Wq,*g1bq,*g1Wk,*g1bk,*g1Wv,*g1bv,*g1We,*g1Ws,*g1bs;
    const float *g2Wq,*g2bq,*g2Wk,*g2bk,*g2Wv,*g2bv,*g2We,*g2Ws,*g2bs;
    float* out;
};

// block-private global scratch (written+read within one CTA across __syncthreads)
__device__ float g_hbuf[(size_t)BB * EE * 16];   // per-edge MLP outputs, by edge id e
__device__ float g_vpe [(size_t)BB * EE * 64];   // per-edge v[src]+ev, by edge id e

struct SM {
    float z[NN * 16];
    float q[NN * 68], k[NN * 68], v[NN * 68];
    float a[NN * 17];
    float root1[NN * 16];
    float acc1[NN * 64];
    float denom1[NN * 4];
    float expl[EE * 4];
    // MLP weights (vectorized rows)
    float4 W1v[48];  float b1[16];
    float4 W2v[64];  float b2[16];
    float4 W3v[64];  float b3[16];
    float lng[16], lnb[16], emb[20];
    // g1 attention weights: transposed [j][u], stride 65 (conflict-free)
    float WqT[16 * 65], WkT[16 * 65], WvT[16 * 65];
    float g1bq[64], g1bk[64], g1bv[64];
    float4 Wev[128];           // We rows as 2x float4
    float WsT[256];            // Ws transposed [j][o]
    float g1bs[16];
    // g2 agent-only state
    float qa[128], roota[32], denom2[4], acc2[128];
    // CSR by dst
    int csr[EE];               // (src<<16)|e
    int rowptr[NN + 1];
    int cursor[NN], deg[NN], etype[NN];
    int agent;
};
static_assert(sizeof(SM) <= 232448, "smem over limit");

__device__ __forceinline__ void cpf(float* d, const float* s, int n, int tid) {
    for (int i = tid; i < n; i += NT) d[i] = s[i];
}

__device__ __forceinline__ void ln16(float* h, const float* g, const float* bb) {
    float m = 0.f;
#pragma unroll
    for (int i = 0; i < 16; i++) m += h[i];
    m *= (1.f / 16.f);
    float var = 0.f;
#pragma unroll
    for (int i = 0; i < 16; i++) { float d = h[i] - m; var += d * d; }
    var *= (1.f / 16.f);
    float inv = rsqrtf(var + 1e-5f);
#pragma unroll
    for (int i = 0; i < 16; i++) h[i] = (h[i] - m) * inv * g[i] + bb[i];
}

__global__ void __launch_bounds__(NT, 1) gnn_kernel(Args A) {
    extern __shared__ unsigned char smraw[];
    SM* s = reinterpret_cast<SM*>(smraw);
    const int b = blockIdx.x;
    const int tid = threadIdx.x;
    const int* ei = A.ei + b * 2 * EE;
    const float* eag = A.ea + (size_t)b * EE * 8;

    // ---- S0: weights -> smem, init ----
    cpf((float*)s->W1v, A.W1, 192, tid);  cpf(s->b1, A.b1, 16, tid);
    cpf((float*)s->W2v, A.W2, 256, tid);  cpf(s->b2, A.b2, 16, tid);
    cpf((float*)s->W3v, A.W3, 256, tid);  cpf(s->b3, A.b3, 16, tid);
    cpf(s->lng, A.lng, 16, tid); cpf(s->lnb, A.lnb, 16, tid);
    cpf(s->emb, A.emb, 20, tid);
    cpf((float*)s->Wev, A.g1We, 512, tid);
    cpf(s->g1bq, A.g1bq, 64, tid); cpf(s->g1bk, A.g1bk, 64, tid);
    cpf(s->g1bv, A.g1bv, 64, tid); cpf(s->g1bs, A.g1bs, 16, tid);
    for (int i = tid; i < 1024; i += NT) {
        const int u = i >> 4, j = i & 15;
        s->WqT[j * 65 + u] = A.g1Wq[i];
        s->WkT[j * 65 + u] = A.g1Wk[i];
        s->WvT[j * 65 + u] = A.g1Wv[i];
    }
    for (int i = tid; i < 256; i += NT) {
        const int o = i >> 4, j = i & 15;
        s->WsT[j * 16 + o] = A.g1Ws[i];
    }
    for (int i = tid; i < NN; i += NT) {
        s->etype[i] = (int)A.nodes[b * NN + i];
        s->deg[i] = 0;
    }
    for (int i = tid; i < 4; i += NT) s->denom2[i] = 0.f;
    for (int i = tid; i < 128; i += NT) s->acc2[i] = 0.f;
    if (tid == 0) s->agent = A.agent[b];
    __syncthreads();

    // ---- S0b: degree histogram ----
    for (int e = tid; e < EE; e += NT) atomicAdd(&s->deg[ei[EE + e]], 1);
    __syncthreads();

    // ---- S0c: prefix sum ----
    if (tid == 0) {
        int run = 0;
        for (int n = 0; n < NN; n++) { s->rowptr[n] = run; s->cursor[n] = run; run += s->deg[n]; }
        s->rowptr[NN] = run;
    }
    __syncthreads();

    // ---- S1a: CSR scatter + per-edge MLP -> g_hbuf ----
    for (int e = tid; e < EE; e += NT) {
        const int src = ei[e], dst = ei[EE + e];
        const int pos = atomicAdd(&s->cursor[dst], 1);
        s->csr[pos] = (src << 16) | e;

        const int t = s->etype[src];
        const float4 xA = *(const float4*)&s->emb[t * 4];
        const float4 xB = *(const float4*)(eag + (size_t)e * 8);
        const float4 xC = *(const float4*)(eag + (size_t)e * 8 + 4);

        float h[16], h2[16];
#pragma unroll
        for (int o = 0; o < 16; o++) {
            const float4 w0 = s->W1v[o * 3], w1 = s->W1v[o * 3 + 1], w2 = s->W1v[o * 3 + 2];
            float acc = s->b1[o]
                + w0.x * xA.x + w0.y * xA.y + w0.z * xA.z + w0.w * xA.w
                + w1.x * xB.x + w1.y * xB.y + w1.z * xB.z + w1.w * xB.w
                + w2.x * xC.x + w2.y * xC.y + w2.z * xC.z + w2.w * xC.w;
            h[o] = fmaxf(acc, 0.f);
        }
        ln16(h, s->lng, s->lnb);
#pragma unroll
        for (int o = 0; o < 16; o++) {
            float acc = s->b2[o];
#pragma unroll
            for (int jq = 0; jq < 4; jq++) {
                const float4 w = s->W2v[o * 4 + jq];
                acc += w.x * h[jq * 4] + w.y * h[jq * 4 + 1] + w.z * h[jq * 4 + 2] + w.w * h[jq * 4 + 3];
            }
            h2[o] = fmaxf(acc, 0.f);
        }
        ln16(h2, s->lng, s->lnb);
#pragma unroll
        for (int o = 0; o < 16; o++) {
            float acc = s->b3[o];
#pragma unroll
            for (int jq = 0; jq < 4; jq++) {
                const float4 w = s->W3v[o * 4 + jq];
                acc += w.x * h2[jq * 4] + w.y * h2[jq * 4 + 1] + w.z * h2[jq * 4 + 2] + w.w * h2[jq * 4 + 3];
            }
            h[o] = fmaxf(acc, 0.f);
        }
        ln16(h, s->lng, s->lnb);

        float4* hp = (float4*)&g_hbuf[((size_t)b * EE + e) * 16];
        hp[0] = make_float4(h[0], h[1], h[2], h[3]);
        hp[1] = make_float4(h[4], h[5], h[6], h[7]);
        hp[2] = make_float4(h[8], h[9], h[10], h[11]);
        hp[3] = make_float4(h[12], h[13], h[14], h[15]);
    }
    __syncthreads();

    // ---- S1b: z = segment_sum(h, dst) via CSR gather (float4) ----
    for (int idx = tid; idx < NN * 4; idx += NT) {
        const int n = idx >> 2, g = idx & 3;
        const int p0 = s->rowptr[n], p1 = s->rowptr[n + 1];
        float4 acc = make_float4(0.f, 0.f, 0.f, 0.f);
        for (int p = p0; p < p1; p++) {
            const int e = s->csr[p] & 0xFFFF;
            const float4 hv = *(const float4*)&g_hbuf[((size_t)b * EE + e) * 16 + g * 4];
            acc.x += hv.x; acc.y += hv.y; acc.z += hv.z; acc.w += hv.w;
        }
        *(float4*)&s->z[n * 16 + g * 4] = acc;
    }
    __syncthreads();

    // ---- S2: q,k,v and root for ALL nodes (transposed weights) ----
    for (int idx = tid; idx < NN * 64; idx += NT) {
        const int n = idx >> 6, u = idx & 63;
        const float* zr = &s->z[n * 16];
        float aq = s->g1bq[u], ak = s->g1bk[u], av = s->g1bv[u];
#pragma unroll
        for (int j = 0; j < 16; j++) {
            const float zj = zr[j];
            aq += s->WqT[j * 65 + u] * zj;
            ak += s->WkT[j * 65 + u] * zj;
            av += s->WvT[j * 65 + u] * zj;
        }
        s->q[n * 68 + u] = aq; s->k[n * 68 + u] = ak; s->v[n * 68 + u] = av;
    }
    for (int idx = tid; idx < NN * 16; idx += NT) {
        const int n = idx >> 4, o = idx & 15;
        float ac = s->g1bs[o];
#pragma unroll
        for (int j = 0; j < 16; j++) ac += s->WsT[j * 16 + o] * s->z[n * 16 + j];
        s->root1[idx] = ac;
    }
    __syncthreads();

    // ---- S3a: all edges: logits -> expl[e], vpe[e] = v[src]+ev ----
    for (int e = tid; e < EE; e += NT) {
        const int src = ei[e], dst = ei[EE + e];
        const float4 eA = *(const float4*)(eag + (size_t)e * 8);
        const float4 eB = *(const float4*)(eag + (size_t)e * 8 + 4);
        const float* qd = &s->q[dst * 68];
        const float* ks = &s->k[src * 68];
        const float* vs = &s->v[src * 68];
        float4* vout = (float4*)&g_vpe[((size_t)b * EE + e) * 64];
#pragma unroll
        for (int hh = 0; hh < 4; hh++) {
            float lg = 0.f;
#pragma unroll
            for (int g = 0; g < 4; g++) {
                const int u0 = hh * 16 + g * 4;
                const float4 q4 = *(const float4*)(qd + u0);
                const float4 k4 = *(const float4*)(ks + u0);
                const float4 v4 = *(const float4*)(vs + u0);
                float ev[4];
#pragma unroll
                for (int t = 0; t < 4; t++) {
                    const float4 wa = s->Wev[(u0 + t) * 2], wb = s->Wev[(u0 + t) * 2 + 1];
                    ev[t] = wa.x * eA.x + wa.y * eA.y + wa.z * eA.z + wa.w * eA.w
                          + wb.x * eB.x + wb.y * eB.y + wb.z * eB.z + wb.w * eB.w;
                }
                lg += q4.x * (k4.x + ev[0]) + q4.y * (k4.y + ev[1])
                    + q4.z * (k4.z + ev[2]) + q4.w * (k4.w + ev[3]);
                vout[u0 >> 2] = make_float4(v4.x + ev[0], v4.y + ev[1], v4.z + ev[2], v4.w + ev[3]);
            }
            s->expl[e * 4 + hh] = __expf(lg * 0.25f);
        }
    }
    __syncthreads();

    // ---- S3b: softmax-weighted gather (all nodes) ----
    for (int idx = tid; idx < NN * 16; idx += NT) {
        const int n = idx >> 4, g = idx & 15;
        const int u0 = g * 4, hh = g >> 2;
        const int p0 = s->rowptr[n], p1 = s->rowptr[n + 1];
        float4 acc = make_float4(0.f, 0.f, 0.f, 0.f);
        for (int p = p0; p < p1; p++) {
            const int e = s->csr[p] & 0xFFFF;
            const float ex = s->expl[e * 4 + hh];
            const float4 vp = *(const float4*)&g_vpe[((size_t)b * EE + e) * 64 + u0];
            acc.x += ex * vp.x; acc.y += ex * vp.y; acc.z += ex * vp.z; acc.w += ex * vp.w;
        }
        *(float4*)&s->acc1[n * 64 + u0] = acc;
    }
    for (int idx = tid; idx < NN * 4; idx += NT) {
        const int n = idx >> 2, hh = idx & 3;
        const int p0 = s->rowptr[n], p1 = s->rowptr[n + 1];
        float d = 0.f;
        for (int p = p0; p < p1; p++) d += s->expl[(s->csr[p] & 0xFFFF) * 4 + hh];
        s->denom1[idx] = d;
    }
    __syncthreads();

    // ---- S4: a = mean_h(acc/denom) + root (all nodes) ----
    for (int idx = tid; idx < NN * 16; idx += NT) {
        const int n = idx >> 4, c = idx & 15;
        float sum = 0.f;
#pragma unroll
        for (int hh = 0; hh < 4; hh++)
            sum += s->acc1[n * 64 + hh * 16 + c] / (s->denom1[n * 4 + hh] + 1e-16f);
        s->a[n * 17 + c] = 0.25f * sum + s->root1[idx];
    }
    __syncthreads();

    const int ag = s->agent;

    // ---- S5: g2 agent q and root ----
    {
        const float* ar = &s->a[ag * 17];
        for (int u = tid; u < 128; u += NT) {
            float ac = A.g2bq[u];
#pragma unroll
            for (int j = 0; j < 16; j++) ac += A.g2Wq[u * 16 + j] * ar[j];
            s->qa[u] = ac;
        }
        for (int c = tid; c < 32; c += NT) {
            float ac = A.g2bs[c];
#pragma unroll
            for (int j = 0; j < 16; j++) ac += A.g2Ws[c * 16 + j] * ar[j];
            s->roota[c] = ac;
        }
    }
    __syncthreads();

    // ---- S6: g2 edges with dst == agent ----
    {
        const int p0 = s->rowptr[ag];
        const int m = s->rowptr[ag + 1] - p0;
        for (int w = tid; w < m * 4; w += NT) {
            const int pe = w >> 2, hh = w & 3;
            const int pk = s->csr[p0 + pe];
            const int e = pk & 0xFFFF, src = pk >> 16;
            const float* eap = eag + (size_t)e * 8;
            float ear[8];
#pragma unroll
            for (int j = 0; j < 8; j++) ear[j] = eap[j];
            const float* ar = &s->a[src * 17];
            float ev[32];
            float lg = 0.f;
#pragma unroll
            for (int c = 0; c < 32; c++) {
                const int u = hh * 32 + c;
                float evv = 0.f;
#pragma unroll
                for (int j = 0; j < 8; j++) evv += A.g2We[u * 8 + j] * ear[j];
                ev[c] = evv;
                float kk = A.g2bk[u];
#pragma unroll
                for (int j = 0; j < 16; j++) kk += A.g2Wk[u * 16 + j] * ar[j];
                lg += s->qa[u] * (kk + evv);
            }
            const float ex = __expf(lg * 0.17677669529663689f);
            atomicAdd(&s->denom2[hh], ex);
#pragma unroll
            for (int c = 0; c < 32; c++) {
                const int u = hh * 32 + c;
                float vv = A.g2bv[u];
#pragma unroll
                for (int j = 0; j < 16; j++) vv += A.g2Wv[u * 16 + j] * ar[j];
                atomicAdd(&s->acc2[u], ex * (vv + ev[c]));
            }
        }
    }
    __syncthreads();

    // ---- S7: output at agent node ----
    for (int c = tid; c < 32; c += NT) {
        float sum = 0.f;
#pragma unroll
        for (int hh = 0; hh < 4; hh++)
            sum += s->acc2[hh * 32 + c] / (s->denom2[hh] + 1e-16f);
        A.out[b * 32 + c] = fmaxf(0.25f * sum + s->roota[c], 0.f);
    }
}

extern "C" void kernel_launch(void* const* d_in, const int* in_sizes, int n_in,
                              void* d_out, int out_size) {
    Args A;
    A.nodes = (const float*)d_in[0];
    A.ei    = (const int*)  d_in[1];
    A.ea    = (const float*)d_in[2];
    A.agent = (const int*)  d_in[3];
    A.emb   = (const float*)d_in[4];
    A.W1 = (const float*)d_in[5];  A.b1 = (const float*)d_in[6];
    A.W2 = (const float*)d_in[7];  A.b2 = (const float*)d_in[8];
    A.W3 = (const float*)d_in[9];  A.b3 = (const float*)d_in[10];
    A.lng = (const float*)d_in[11]; A.lnb = (const float*)d_in[12];
    A.g1Wq = (const float*)d_in[13]; A.g1bq = (const float*)d_in[14];
    A.g1Wk = (const float*)d_in[15]; A.g1bk = (const float*)d_in[16];
    A.g1Wv = (const float*)d_in[17]; A.g1bv = (const float*)d_in[18];
    A.g1We = (const float*)d_in[19];
    A.g1Ws = (const float*)d_in[20]; A.g1bs = (const float*)d_in[21];
    A.g2Wq = (const float*)d_in[22]; A.g2bq = (const float*)d_in[23];
    A.g2Wk = (const float*)d_in[24]; A.g2bk = (const float*)d_in[25];
    A.g2Wv = (const float*)d_in[26]; A.g2bv = (const float*)d_in[27];
    A.g2We = (const float*)d_in[28];
    A.g2Ws = (const float*)d_in[29]; A.g2bs = (const float*)d_in[30];
    A.out = (float*)d_out;

    cudaFuncSetAttribute(gnn_kernel, cudaFuncAttributeMaxDynamicSharedMemorySize,
                         (int)sizeof(SM));
    gnn_kernel<<<BB, NT, sizeof(SM)>>>(A);
}

// round 5
// speedup vs baseline: 1.2943x; 1.2943x over previous
#include <cuda_runtime.h>

#define BB 128
#define NN 100
#define EE 3200
#define NT 768

struct Args {
    const float* nodes;
    const int*   ei;
    const float* ea;
    const int*   agent;
    const float* emb;
    const float *W1,*b1,*W2,*b2,*W3,*b3,*lng,*lnb;
    const float *g1Wq,*g1bq,*g1Wk,*g1bk,*g1Wv,*g1bv,*g1We,*g1Ws,*g1bs;
    const float *g2Wq,*g2bq,*g2Wk,*g2bk,*g2Wv,*g2bv,*g2We,*g2Ws,*g2bs;
    float* out;
};

// block-private global scratch (written+read within one CTA across __syncthreads)
__device__ float g_hbuf[(size_t)BB * EE * 16];   // per-edge MLP outputs, by edge id e

struct SM {
    float z[NN * 16];
    float q[NN * 68], k[NN * 68], v[NN * 68];
    float root1[NN * 16];
    float acc1[NN * 64];
    float denom1[NN * 4];
    float expl[EE * 4];        // [alias] a[NN*17] lives here after S3b (expl dead)
    float qwe[NN * 32];        // qWe[n,h,j] in S2..S3a; wea[n,h,j] after (disjoint lifetimes)
    // MLP weights (vectorized rows)
    float4 W1v[48];  float b1[16];
    float4 W2v[64];  float b2[16];
    float4 W3v[64];  float b3[16];
    float lng[16], lnb[16], emb[20];
    // g1 attention weights: transposed [j][u], stride 65 (conflict-free)
    float WqT[16 * 65], WkT[16 * 65], WvT[16 * 65];
    float g1bq[64], g1bk[64], g1bv[64];
    float4 Wev[128];           // We rows as 2x float4 (row-major [u][j])
    float WsT[256];            // Ws transposed [j][o]
    float g1bs[16];
    // g2 agent-only state
    float qa[128], roota[32], denom2[4], acc2[128];
    // CSR by dst
    int csr[EE];               // (src<<16)|e
    int rowptr[NN + 1];
    int cursor[NN], deg[NN], etype[NN];
    int agent;
};
static_assert(sizeof(SM) <= 232448, "smem over limit");

__device__ __forceinline__ void cpf(float* d, const float* s, int n, int tid) {
    for (int i = tid; i < n; i += NT) d[i] = s[i];
}

__device__ __forceinline__ void ln16(float* h, const float* g, const float* bb) {
    float m = 0.f;
#pragma unroll
    for (int i = 0; i < 16; i++) m += h[i];
    m *= (1.f / 16.f);
    float var = 0.f;
#pragma unroll
    for (int i = 0; i < 16; i++) { float d = h[i] - m; var += d * d; }
    var *= (1.f / 16.f);
    float inv = rsqrtf(var + 1e-5f);
#pragma unroll
    for (int i = 0; i < 16; i++) h[i] = (h[i] - m) * inv * g[i] + bb[i];
}

__global__ void __launch_bounds__(NT, 1) gnn_kernel(Args A) {
    extern __shared__ unsigned char smraw[];
    SM* s = reinterpret_cast<SM*>(smraw);
    const int b = blockIdx.x;
    const int tid = threadIdx.x;
    const int* ei = A.ei + b * 2 * EE;
    const float* eag = A.ea + (size_t)b * EE * 8;
    const float* wef = (const float*)s->Wev;
    float* aarr = s->expl;   // alias: a[n*17+c], valid after S3b

    // ---- S0: weights -> smem, init ----
    cpf((float*)s->W1v, A.W1, 192, tid);  cpf(s->b1, A.b1, 16, tid);
    cpf((float*)s->W2v, A.W2, 256, tid);  cpf(s->b2, A.b2, 16, tid);
    cpf((float*)s->W3v, A.W3, 256, tid);  cpf(s->b3, A.b3, 16, tid);
    cpf(s->lng, A.lng, 16, tid); cpf(s->lnb, A.lnb, 16, tid);
    cpf(s->emb, A.emb, 20, tid);
    cpf((float*)s->Wev, A.g1We, 512, tid);
    cpf(s->g1bq, A.g1bq, 64, tid); cpf(s->g1bk, A.g1bk, 64, tid);
    cpf(s->g1bv, A.g1bv, 64, tid); cpf(s->g1bs, A.g1bs, 16, tid);
    for (int i = tid; i < 1024; i += NT) {
        const int u = i >> 4, j = i & 15;
        s->WqT[j * 65 + u] = A.g1Wq[i];
        s->WkT[j * 65 + u] = A.g1Wk[i];
        s->WvT[j * 65 + u] = A.g1Wv[i];
    }
    for (int i = tid; i < 256; i += NT) {
        const int o = i >> 4, j = i & 15;
        s->WsT[j * 16 + o] = A.g1Ws[i];
    }
    for (int i = tid; i < NN; i += NT) {
        s->etype[i] = (int)A.nodes[b * NN + i];
        s->deg[i] = 0;
    }
    for (int i = tid; i < 4; i += NT) s->denom2[i] = 0.f;
    for (int i = tid; i < 128; i += NT) s->acc2[i] = 0.f;
    if (tid == 0) s->agent = A.agent[b];
    __syncthreads();

    // ---- S0b: degree histogram ----
    for (int e = tid; e < EE; e += NT) atomicAdd(&s->deg[ei[EE + e]], 1);
    __syncthreads();

    // ---- S0c: warp-parallel prefix sum (warp 0) ----
    if (tid < 32) {
        int d0[4]; int t = 0;
#pragma unroll
        for (int u = 0; u < 4; u++) {
            const int n = tid * 4 + u;
            d0[u] = (n < NN) ? s->deg[n] : 0;
            t += d0[u];
        }
        int incl = t;
#pragma unroll
        for (int o = 1; o < 32; o <<= 1) {
            const int vv = __shfl_up_sync(0xFFFFFFFFu, incl, o);
            if (tid >= o) incl += vv;
        }
        int run = incl - t;
#pragma unroll
        for (int u = 0; u < 4; u++) {
            const int n = tid * 4 + u;
            if (n < NN) { s->rowptr[n] = run; run += d0[u]; }
        }
        if (tid == 31) s->rowptr[NN] = incl;
    }
    __syncthreads();
    for (int n = tid; n < NN; n += NT) s->cursor[n] = s->rowptr[n];
    __syncthreads();

    // ---- S1a: CSR scatter + per-edge MLP -> g_hbuf ----
    for (int e = tid; e < EE; e += NT) {
        const int src = ei[e], dst = ei[EE + e];
        const int pos = atomicAdd(&s->cursor[dst], 1);
        s->csr[pos] = (src << 16) | e;

        const int t = s->etype[src];
        const float4 xA = *(const float4*)&s->emb[t * 4];
        const float4 xB = *(const float4*)(eag + (size_t)e * 8);
        const float4 xC = *(const float4*)(eag + (size_t)e * 8 + 4);

        float h[16], h2[16];
#pragma unroll
        for (int o = 0; o < 16; o++) {
            const float4 w0 = s->W1v[o * 3], w1 = s->W1v[o * 3 + 1], w2 = s->W1v[o * 3 + 2];
            float acc = s->b1[o]
                + w0.x * xA.x + w0.y * xA.y + w0.z * xA.z + w0.w * xA.w
                + w1.x * xB.x + w1.y * xB.y + w1.z * xB.z + w1.w * xB.w
                + w2.x * xC.x + w2.y * xC.y + w2.z * xC.z + w2.w * xC.w;
            h[o] = fmaxf(acc, 0.f);
        }
        ln16(h, s->lng, s->lnb);
#pragma unroll
        for (int o = 0; o < 16; o++) {
            float acc = s->b2[o];
#pragma unroll
            for (int jq = 0; jq < 4; jq++) {
                const float4 w = s->W2v[o * 4 + jq];
                acc += w.x * h[jq * 4] + w.y * h[jq * 4 + 1] + w.z * h[jq * 4 + 2] + w.w * h[jq * 4 + 3];
            }
            h2[o] = fmaxf(acc, 0.f);
        }
        ln16(h2, s->lng, s->lnb);
#pragma unroll
        for (int o = 0; o < 16; o++) {
            float acc = s->b3[o];
#pragma unroll
            for (int jq = 0; jq < 4; jq++) {
                const float4 w = s->W3v[o * 4 + jq];
                acc += w.x * h2[jq * 4] + w.y * h2[jq * 4 + 1] + w.z * h2[jq * 4 + 2] + w.w * h2[jq * 4 + 3];
            }
            h[o] = fmaxf(acc, 0.f);
        }
        ln16(h, s->lng, s->lnb);

        float4* hp = (float4*)&g_hbuf[((size_t)b * EE + e) * 16];
        hp[0] = make_float4(h[0], h[1], h[2], h[3]);
        hp[1] = make_float4(h[4], h[5], h[6], h[7]);
        hp[2] = make_float4(h[8], h[9], h[10], h[11]);
        hp[3] = make_float4(h[12], h[13], h[14], h[15]);
    }
    __syncthreads();

    // ---- S1b: z = segment_sum(h, dst) via CSR gather (float4) ----
    for (int idx = tid; idx < NN * 4; idx += NT) {
        const int n = idx >> 2, g = idx & 3;
        const int p0 = s->rowptr[n], p1 = s->rowptr[n + 1];
        float4 acc = make_float4(0.f, 0.f, 0.f, 0.f);
        for (int p = p0; p < p1; p++) {
            const int e = s->csr[p] & 0xFFFF;
            const float4 hv = *(const float4*)&g_hbuf[((size_t)b * EE + e) * 16 + g * 4];
            acc.x += hv.x; acc.y += hv.y; acc.z += hv.z; acc.w += hv.w;
        }
        *(float4*)&s->z[n * 16 + g * 4] = acc;
    }
    __syncthreads();

    // ---- S2: q,k,v and root for ALL nodes (transposed weights) ----
    for (int idx = tid; idx < NN * 64; idx += NT) {
        const int n = idx >> 6, u = idx & 63;
        const float* zr = &s->z[n * 16];
        float aq = s->g1bq[u], ak = s->g1bk[u], av = s->g1bv[u];
#pragma unroll
        for (int j = 0; j < 16; j++) {
            const float zj = zr[j];
            aq += s->WqT[j * 65 + u] * zj;
            ak += s->WkT[j * 65 + u] * zj;
            av += s->WvT[j * 65 + u] * zj;
        }
        s->q[n * 68 + u] = aq; s->k[n * 68 + u] = ak; s->v[n * 68 + u] = av;
    }
    for (int idx = tid; idx < NN * 16; idx += NT) {
        const int n = idx >> 4, o = idx & 15;
        float ac = s->g1bs[o];
#pragma unroll
        for (int j = 0; j < 16; j++) ac += s->WsT[j * 16 + o] * s->z[n * 16 + j];
        s->root1[idx] = ac;
    }
    __syncthreads();

    // ---- S2b: qWe[n,h,j] = sum_c q[n,h*16+c] * We[h*16+c, j] ----
    for (int idx = tid; idx < NN * 32; idx += NT) {
        const int n = idx >> 5, r = idx & 31;
        const int hh = r >> 3, j = r & 7;
        const float* qr = &s->q[n * 68 + hh * 16];
        float acc = 0.f;
#pragma unroll
        for (int c = 0; c < 16; c++) acc += qr[c] * wef[(hh * 16 + c) * 8 + j];
        s->qwe[idx] = acc;
    }
    __syncthreads();

    // ---- S3a: per-edge logits: lg = q.k + qWe[dst].ea ----
    for (int e = tid; e < EE; e += NT) {
        const int src = ei[e], dst = ei[EE + e];
        const float4 eA = *(const float4*)(eag + (size_t)e * 8);
        const float4 eB = *(const float4*)(eag + (size_t)e * 8 + 4);
        const float* qd = &s->q[dst * 68];
        const float* ks = &s->k[src * 68];
        const float* qw = &s->qwe[dst * 32];
#pragma unroll
        for (int hh = 0; hh < 4; hh++) {
            float lg = 0.f;
#pragma unroll
            for (int g = 0; g < 4; g++) {
                const int u0 = hh * 16 + g * 4;
                const float4 q4 = *(const float4*)(qd + u0);
                const float4 k4 = *(const float4*)(ks + u0);
                lg += q4.x * k4.x + q4.y * k4.y + q4.z * k4.z + q4.w * k4.w;
            }
            const float4 wa = *(const float4*)(qw + hh * 8);
            const float4 wb = *(const float4*)(qw + hh * 8 + 4);
            lg += wa.x * eA.x + wa.y * eA.y + wa.z * eA.z + wa.w * eA.w
                + wb.x * eB.x + wb.y * eB.y + wb.z * eB.z + wb.w * eB.w;
            s->expl[e * 4 + hh] = __expf(lg * 0.25f);
        }
    }
    __syncthreads();

    // ---- S3b-1: wea[n,h,j] = sum_e expl[e,h] * ea[e,j]  (overwrites qwe) ----
    for (int idx = tid; idx < NN * 8; idx += NT) {
        const int n = idx >> 3, r = idx & 7;
        const int hh = r >> 1, half = r & 1;
        const int p0 = s->rowptr[n], p1 = s->rowptr[n + 1];
        float4 acc = make_float4(0.f, 0.f, 0.f, 0.f);
        for (int p = p0; p < p1; p++) {
            const int e = s->csr[p] & 0xFFFF;
            const float ex = s->expl[e * 4 + hh];
            const float4 ea4 = *(const float4*)(eag + (size_t)e * 8 + half * 4);
            acc.x += ex * ea4.x; acc.y += ex * ea4.y; acc.z += ex * ea4.z; acc.w += ex * ea4.w;
        }
        *(float4*)&s->qwe[n * 32 + hh * 8 + half * 4] = acc;
    }
    // ---- S3b-2: denominators ----
    for (int idx = tid; idx < NN * 4; idx += NT) {
        const int n = idx >> 2, hh = idx & 3;
        const int p0 = s->rowptr[n], p1 = s->rowptr[n + 1];
        float d = 0.f;
        for (int p = p0; p < p1; p++) d += s->expl[(s->csr[p] & 0xFFFF) * 4 + hh];
        s->denom1[idx] = d;
    }
    __syncthreads();

    // ---- S3b-3: acc1[n,u] = sum_e expl*v[src,u]  +  We[u,:].wea[n,h,:] ----
    for (int idx = tid; idx < NN * 16; idx += NT) {
        const int n = idx >> 4, g = idx & 15;
        const int u0 = g * 4, hh = g >> 2;
        const int p0 = s->rowptr[n], p1 = s->rowptr[n + 1];
        float4 acc = make_float4(0.f, 0.f, 0.f, 0.f);
        for (int p = p0; p < p1; p++) {
            const int pk = s->csr[p];
            const int e = pk & 0xFFFF, src = pk >> 16;
            const float ex = s->expl[e * 4 + hh];
            const float4 v4 = *(const float4*)&s->v[src * 68 + u0];
            acc.x += ex * v4.x; acc.y += ex * v4.y; acc.z += ex * v4.z; acc.w += ex * v4.w;
        }
        const float* we_n = &s->qwe[n * 32 + hh * 8];
        float add[4];
#pragma unroll
        for (int t = 0; t < 4; t++) {
            const int u = u0 + t;
            float a2 = 0.f;
#pragma unroll
            for (int j = 0; j < 8; j++) a2 += wef[u * 8 + j] * we_n[j];
            add[t] = a2;
        }
        acc.x += add[0]; acc.y += add[1]; acc.z += add[2]; acc.w += add[3];
        *(float4*)&s->acc1[n * 64 + u0] = acc;
    }
    __syncthreads();

    // ---- S4: a = mean_h(acc/denom) + root (a aliases expl region) ----
    for (int idx = tid; idx < NN * 16; idx += NT) {
        const int n = idx >> 4, c = idx & 15;
        float sum = 0.f;
#pragma unroll
        for (int hh = 0; hh < 4; hh++)
            sum += s->acc1[n * 64 + hh * 16 + c] / (s->denom1[n * 4 + hh] + 1e-16f);
        aarr[n * 17 + c] = 0.25f * sum + s->root1[idx];
    }
    __syncthreads();

    const int ag = s->agent;

    // ---- S5: g2 agent q and root ----
    {
        const float* ar = &aarr[ag * 17];
        for (int u = tid; u < 128; u += NT) {
            float ac = A.g2bq[u];
#pragma unroll
            for (int j = 0; j < 16; j++) ac += A.g2Wq[u * 16 + j] * ar[j];
            s->qa[u] = ac;
        }
        for (int c = tid; c < 32; c += NT) {
            float ac = A.g2bs[c];
#pragma unroll
            for (int j = 0; j < 16; j++) ac += A.g2Ws[c * 16 + j] * ar[j];
            s->roota[c] = ac;
        }
    }
    __syncthreads();

    // ---- S6: g2 edges with dst == agent ----
    {
        const int p0 = s->rowptr[ag];
        const int m = s->rowptr[ag + 1] - p0;
        for (int w = tid; w < m * 4; w += NT) {
            const int pe = w >> 2, hh = w & 3;
            const int pk = s->csr[p0 + pe];
            const int e = pk & 0xFFFF, src = pk >> 16;
            const float* eap = eag + (size_t)e * 8;
            float ear[8];
#pragma unroll
            for (int j = 0; j < 8; j++) ear[j] = eap[j];
            const float* ar = &aarr[src * 17];
            float ev[32];
            float lg = 0.f;
#pragma unroll
            for (int c = 0; c < 32; c++) {
                const int u = hh * 32 + c;
                float evv = 0.f;
#pragma unroll
                for (int j = 0; j < 8; j++) evv += A.g2We[u * 8 + j] * ear[j];
                ev[c] = evv;
                float kk = A.g2bk[u];
#pragma unroll
                for (int j = 0; j < 16; j++) kk += A.g2Wk[u * 16 + j] * ar[j];
                lg += s->qa[u] * (kk + evv);
            }
            const float ex = __expf(lg * 0.17677669529663689f);
            atomicAdd(&s->denom2[hh], ex);
#pragma unroll
            for (int c = 0; c < 32; c++) {
                const int u = hh * 32 + c;
                float vv = A.g2bv[u];
#pragma unroll
                for (int j = 0; j < 16; j++) vv += A.g2Wv[u * 16 + j] * ar[j];
                atomicAdd(&s->acc2[u], ex * (vv + ev[c]));
            }
        }
    }
    __syncthreads();

    // ---- S7: output at agent node ----
    for (int c = tid; c < 32; c += NT) {
        float sum = 0.f;
#pragma unroll
        for (int hh = 0; hh < 4; hh++)
            sum += s->acc2[hh * 32 + c] / (s->denom2[hh] + 1e-16f);
        A.out[b * 32 + c] = fmaxf(0.25f * sum + s->roota[c], 0.f);
    }
}

extern "C" void kernel_launch(void* const* d_in, const int* in_sizes, int n_in,
                              void* d_out, int out_size) {
    Args A;
    A.nodes = (const float*)d_in[0];
    A.ei    = (const int*)  d_in[1];
    A.ea    = (const float*)d_in[2];
    A.agent = (const int*)  d_in[3];
    A.emb   = (const float*)d_in[4];
    A.W1 = (const float*)d_in[5];  A.b1 = (const float*)d_in[6];
    A.W2 = (const float*)d_in[7];  A.b2 = (const float*)d_in[8];
    A.W3 = (const float*)d_in[9];  A.b3 = (const float*)d_in[10];
    A.lng = (const float*)d_in[11]; A.lnb = (const float*)d_in[12];
    A.g1Wq = (const float*)d_in[13]; A.g1bq = (const float*)d_in[14];
    A.g1Wk = (const float*)d_in[15]; A.g1bk = (const float*)d_in[16];
    A.g1Wv = (const float*)d_in[17]; A.g1bv = (const float*)d_in[18];
    A.g1We = (const float*)d_in[19];
    A.g1Ws = (const float*)d_in[20]; A.g1bs = (const float*)d_in[21];
    A.g2Wq = (const float*)d_in[22]; A.g2bq = (const float*)d_in[23];
    A.g2Wk = (const float*)d_in[24]; A.g2bk = (const float*)d_in[25];
    A.g2Wv = (const float*)d_in[26]; A.g2bv = (const float*)d_in[27];
    A.g2We = (const float*)d_in[28];
    A.g2Ws = (const float*)d_in[29]; A.g2bs = (const float*)d_in[30];
    A.out = (float*)d_out;

    cudaFuncSetAttribute(gnn_kernel, cudaFuncAttributeMaxDynamicSharedMemorySize,
                         (int)sizeof(SM));
    gnn_kernel<<<BB, NT, sizeof(SM)>>>(A);
}